// round 1
// baseline (speedup 1.0000x reference)
#include <cuda_runtime.h>

#define B_ROWS   65536
#define KPOS     6
#define KNEG     30
#define NTARG    36      // KPOS + KNEG
#define NGRAMS   12
#define D2       25      // EMBED=50 floats = 25 float2

#define GRID     1024
#define TPB      256
#define WPB      (TPB / 32)
#define NWARPS   (GRID * WPB)

__device__ float g_partial[GRID];

__device__ __forceinline__ float softplusf(float x) {
    // stable: max(x,0) + log(1 + exp(-|x|)); values here are tiny so fast intrinsics suffice
    return fmaxf(x, 0.0f) + __logf(1.0f + __expf(-fabsf(x)));
}

__global__ void __launch_bounds__(TPB)
fasttext_main(const int* __restrict__ input_labels,
              const int* __restrict__ pos_labels,
              const int* __restrict__ neg_labels,
              const int* __restrict__ trigram_idx,
              const int* __restrict__ ngram_mask,
              const float2* __restrict__ cW,
              const float2* __restrict__ bW,
              const float2* __restrict__ tW)
{
    const int lane = threadIdx.x & 31;
    const int warp = threadIdx.x >> 5;
    const int gw   = blockIdx.x * WPB + warp;
    const unsigned FULL = 0xFFFFFFFFu;

    float lacc = 0.0f;   // per-lane loss accumulator across this warp's rows

    for (int b = gw; b < B_ROWS; b += NWARPS) {
        // ---- lane-distributed coalesced index loads ----
        const int ci   = input_labels[b];                                  // uniform
        const int pidx = (lane < KPOS)   ? pos_labels[b * KPOS + lane]   : 0;
        const int nidx = (lane < KNEG)   ? neg_labels[b * KNEG + lane]   : 0;
        // pack mask into the index: -1 means masked-out
        int tpack = -1;
        if (lane < NGRAMS) {
            int ti = trigram_idx[b * NGRAMS + lane];
            int mk = ngram_mask[b * NGRAMS + lane];
            tpack = mk ? ti : -1;
        }

        const bool act = (lane < D2);

        // ---- build context vector m (float2 per lane, lanes 0..24) ----
        float2 m = act ? cW[ci * D2 + lane] : make_float2(0.f, 0.f);
        #pragma unroll
        for (int n = 0; n < NGRAMS; n++) {
            int ti = __shfl_sync(FULL, tpack, n);     // uniform across warp
            if (ti >= 0) {                            // warp-uniform branch
                if (act) {
                    float2 t = tW[ti * D2 + lane];
                    m.x += t.x; m.y += t.y;
                }
            }
        }

        // ---- 36 dot products; stage score k on lane k ----
        float s_lo = 0.f;   // scores k = 0..31 on lane k
        float s_hi = 0.f;   // scores k = 32..35 on lanes 0..3
        #pragma unroll
        for (int k = 0; k < NTARG; k++) {
            int t = (k < KPOS) ? __shfl_sync(FULL, pidx, k)
                               : __shfl_sync(FULL, nidx, k - KPOS);
            float p = 0.f;
            if (act) {
                float2 e = bW[t * D2 + lane];
                p = fmaf(m.x, e.x, m.y * e.y);
            }
            p += __shfl_xor_sync(FULL, p, 16);
            p += __shfl_xor_sync(FULL, p, 8);
            p += __shfl_xor_sync(FULL, p, 4);
            p += __shfl_xor_sync(FULL, p, 2);
            p += __shfl_xor_sync(FULL, p, 1);
            // softplus(-s) for positives, softplus(+s) for negatives
            if (k < KPOS) p = -p;
            if (k < 32) { if (lane == k)      s_lo = p; }
            else        { if (lane == k - 32) s_hi = p; }
        }

        // vectorized softplus: every lane handles its staged score(s)
        lacc += softplusf(s_lo);
        if (lane < NTARG - 32) lacc += softplusf(s_hi);
    }

    // ---- warp reduce lane accumulators ----
    lacc += __shfl_xor_sync(FULL, lacc, 16);
    lacc += __shfl_xor_sync(FULL, lacc, 8);
    lacc += __shfl_xor_sync(FULL, lacc, 4);
    lacc += __shfl_xor_sync(FULL, lacc, 2);
    lacc += __shfl_xor_sync(FULL, lacc, 1);

    __shared__ float sred[WPB];
    if (lane == 0) sred[warp] = lacc;
    __syncthreads();
    if (threadIdx.x == 0) {
        float s = 0.f;
        #pragma unroll
        for (int i = 0; i < WPB; i++) s += sred[i];
        g_partial[blockIdx.x] = s;
    }
}

__global__ void __launch_bounds__(256)
fasttext_reduce(float* __restrict__ out)
{
    __shared__ float sh[256];
    float s = 0.f;
    for (int i = threadIdx.x; i < GRID; i += 256) s += g_partial[i];
    sh[threadIdx.x] = s;
    __syncthreads();
    for (int off = 128; off > 0; off >>= 1) {
        if (threadIdx.x < off) sh[threadIdx.x] += sh[threadIdx.x + off];
        __syncthreads();
    }
    if (threadIdx.x == 0) out[0] = sh[0];
}

extern "C" void kernel_launch(void* const* d_in, const int* in_sizes, int n_in,
                              void* d_out, int out_size)
{
    const int*    input_labels = (const int*)d_in[0];
    const int*    pos_labels   = (const int*)d_in[1];
    const int*    neg_labels   = (const int*)d_in[2];
    const int*    trigram_idx  = (const int*)d_in[3];
    const int*    ngram_mask   = (const int*)d_in[4];
    const float2* cW           = (const float2*)d_in[5];
    const float2* bW           = (const float2*)d_in[6];
    const float2* tW           = (const float2*)d_in[7];

    fasttext_main<<<GRID, TPB>>>(input_labels, pos_labels, neg_labels,
                                 trigram_idx, ngram_mask, cW, bW, tW);
    fasttext_reduce<<<1, 256>>>((float*)d_out);
}

// round 2
// speedup vs baseline: 1.1102x; 1.1102x over previous
#include <cuda_runtime.h>

#define B_ROWS   65536
#define KPOS     6
#define KNEG     30
#define NTARG    36      // KPOS + KNEG
#define NGRAMS   12
#define D2       25      // EMBED=50 floats = 25 float2
#define NGROUP   9       // 36 targets in groups of 4

#define GRID     1184    // 8 blocks/SM * 148 SMs
#define TPB      256
#define WPB      (TPB / 32)
#define NWARPS   (GRID * WPB)

__device__ float g_partial[GRID];
__device__ int   g_ticket = 0;

__device__ __forceinline__ float softplusf(float x) {
    return fmaxf(x, 0.0f) + __logf(1.0f + __expf(-fabsf(x)));
}

__global__ void __launch_bounds__(TPB, 4)
fasttext_fused(const int* __restrict__ input_labels,
               const int* __restrict__ pos_labels,
               const int* __restrict__ neg_labels,
               const int* __restrict__ trigram_idx,
               const int* __restrict__ ngram_mask,
               const float2* __restrict__ cW,
               const float2* __restrict__ bW,
               const float2* __restrict__ tW,
               float* __restrict__ out)
{
    const int lane = threadIdx.x & 31;
    const int warp = threadIdx.x >> 5;
    const int gw   = blockIdx.x * WPB + warp;
    const unsigned FULL = 0xFFFFFFFFu;
    const bool act = (lane < D2);

    float lacc = 0.0f;

    for (int b = gw; b < B_ROWS; b += NWARPS) {
        // ---- coalesced, lane-distributed index loads ----
        const int ci   = input_labels[b];
        const int pidx = (lane < KPOS) ? pos_labels[b * KPOS + lane] : 0;
        const int nidx = (lane < KNEG) ? neg_labels[b * KNEG + lane] : 0;
        int tpack = -1;
        if (lane < NGRAMS) {
            int ti = trigram_idx[b * NGRAMS + lane];
            int mk = ngram_mask[b * NGRAMS + lane];
            tpack = mk ? ti : -1;
        }

        // ---- context vector m: float2 per lane, lanes 0..24 ----
        float2 m = act ? cW[ci * D2 + lane] : make_float2(0.f, 0.f);
        #pragma unroll
        for (int n = 0; n < NGRAMS; n++) {
            int ti = __shfl_sync(FULL, tpack, n);   // warp-uniform
            if (ti >= 0) {
                if (act) {
                    float2 t = tW[ti * D2 + lane];
                    m.x += t.x; m.y += t.y;
                }
            }
        }

        // ---- 36 dots in 9 groups of 4, packed butterfly reduction ----
        float s_lo = 0.f;   // score of target k staged on lane k (k=0..31)
        float s_hi = 0.f;   // targets 32..35 staged on lanes 0..3
        #pragma unroll
        for (int g = 0; g < NGROUP; g++) {
            float p[4];
            #pragma unroll
            for (int j = 0; j < 4; j++) {
                const int t = 4 * g + j;                     // compile-time
                int ti = (t < KPOS) ? __shfl_sync(FULL, pidx, t)
                                    : __shfl_sync(FULL, nidx, t - KPOS);
                float pp = 0.f;
                if (act) {
                    float2 e = bW[ti * D2 + lane];
                    pp = fmaf(m.x, e.x, m.y * e.y);
                }
                p[j] = pp;
            }
            // redundant stages: every lane keeps (lane mod 8)-class partial
            #pragma unroll
            for (int j = 0; j < 4; j++) {
                p[j] += __shfl_xor_sync(FULL, p[j], 16);
                p[j] += __shfl_xor_sync(FULL, p[j], 8);
            }
            // select this lane's quarter-target, finish shared stages
            const int q = lane >> 3;
            float v = (q == 0) ? p[0] : (q == 1) ? p[1] : (q == 2) ? p[2] : p[3];
            v += __shfl_xor_sync(FULL, v, 4);
            v += __shfl_xor_sync(FULL, v, 2);
            v += __shfl_xor_sync(FULL, v, 1);
            // permute: lane l grabs full sum of target 4g + (l & 3)
            float tv = __shfl_sync(FULL, v, (lane & 3) << 3);
            if (g < 8) { if ((lane >> 2) == g) s_lo = tv; }
            else       { if (lane < 4)         s_hi = tv; }
        }

        // vectorized softplus: lane k handles target k (pos targets negated)
        float x = (lane < KPOS) ? -s_lo : s_lo;
        lacc += softplusf(x);
        if (lane < NTARG - 32) lacc += softplusf(s_hi);
    }

    // ---- warp reduce ----
    lacc += __shfl_xor_sync(FULL, lacc, 16);
    lacc += __shfl_xor_sync(FULL, lacc, 8);
    lacc += __shfl_xor_sync(FULL, lacc, 4);
    lacc += __shfl_xor_sync(FULL, lacc, 2);
    lacc += __shfl_xor_sync(FULL, lacc, 1);

    __shared__ float sred[WPB];
    __shared__ int   slast;
    if (lane == 0) sred[warp] = lacc;
    __syncthreads();
    if (threadIdx.x == 0) {
        float s = 0.f;
        #pragma unroll
        for (int i = 0; i < WPB; i++) s += sred[i];
        g_partial[blockIdx.x] = s;
        __threadfence();
        int t = atomicAdd(&g_ticket, 1);
        slast = (t == GRID - 1) ? 1 : 0;
    }
    __syncthreads();

    // ---- last block performs the deterministic final reduction ----
    if (slast) {
        __threadfence();
        float s = 0.f;
        for (int i = threadIdx.x; i < GRID; i += TPB) s += g_partial[i];
        // warp reduce
        s += __shfl_xor_sync(FULL, s, 16);
        s += __shfl_xor_sync(FULL, s, 8);
        s += __shfl_xor_sync(FULL, s, 4);
        s += __shfl_xor_sync(FULL, s, 2);
        s += __shfl_xor_sync(FULL, s, 1);
        __shared__ float fred[WPB];
        if (lane == 0) fred[warp] = s;
        __syncthreads();
        if (threadIdx.x == 0) {
            float tot = 0.f;
            #pragma unroll
            for (int i = 0; i < WPB; i++) tot += fred[i];
            out[0] = tot;
            g_ticket = 0;   // reset for next graph replay
        }
    }
}

extern "C" void kernel_launch(void* const* d_in, const int* in_sizes, int n_in,
                              void* d_out, int out_size)
{
    const int*    input_labels = (const int*)d_in[0];
    const int*    pos_labels   = (const int*)d_in[1];
    const int*    neg_labels   = (const int*)d_in[2];
    const int*    trigram_idx  = (const int*)d_in[3];
    const int*    ngram_mask   = (const int*)d_in[4];
    const float2* cW           = (const float2*)d_in[5];
    const float2* bW           = (const float2*)d_in[6];
    const float2* tW           = (const float2*)d_in[7];

    fasttext_fused<<<GRID, TPB>>>(input_labels, pos_labels, neg_labels,
                                  trigram_idx, ngram_mask, cW, bW, tW,
                                  (float*)d_out);
}